// round 3
// baseline (speedup 1.0000x reference)
#include <cuda_runtime.h>
#include <math.h>

// Problem constants (hard-coded in the reference)
#define N_ROWS 8000
#define D_DIM  9

// Scratch: device globals (no allocation allowed in kernel_launch)
__device__ float g_sdiff[N_ROWS];  // s2[i] - s1[i]
__device__ float g_f1[N_ROWS];
__device__ float g_f2[N_ROWS];
__device__ float g_wbar[N_ROWS];   // w1_bar[i] = sigmoid(cumsum(sdiff)[i])

// ---------------------------------------------------------------------------
// K1: per-row reductions.  One thread = one row (9 floats).
// s1 = sum_d ((x-c1)/a1)^2 ; s2 = sum_d ((x-c2)/a2)^2
// f1 = x . w_fc1 + b_fc1   ; f2 = x . w_fc2 + b_fc2
// ---------------------------------------------------------------------------
__global__ void k1_rowstats(const float* __restrict__ x,
                            const float* __restrict__ a1p,
                            const float* __restrict__ c1p,
                            const float* __restrict__ a2p,
                            const float* __restrict__ c2p,
                            const float* __restrict__ w1,
                            const float* __restrict__ b1,
                            const float* __restrict__ w2,
                            const float* __restrict__ b2)
{
    int i = blockIdx.x * blockDim.x + threadIdx.x;
    if (i >= N_ROWS) return;

    const float a1 = a1p[0], c1 = c1p[0], a2 = a2p[0], c2 = c2p[0];
    const float inv_a1 = 1.0f / a1, inv_a2 = 1.0f / a2;

    const float* xr = x + (size_t)i * D_DIM;

    float s1 = 0.f, s2 = 0.f, f1 = 0.f, f2 = 0.f;
#pragma unroll
    for (int d = 0; d < D_DIM; d++) {
        float xv = xr[d];
        float t1 = (xv - c1) * inv_a1;
        float t2 = (xv - c2) * inv_a2;
        s1 = fmaf(t1, t1, s1);
        s2 = fmaf(t2, t2, s2);
        f1 = fmaf(xv, w1[d], f1);
        f2 = fmaf(xv, w2[d], f2);
    }
    g_sdiff[i] = s2 - s1;
    g_f1[i] = f1 + b1[0];
    g_f2[i] = f2 + b2[0];
}

// ---------------------------------------------------------------------------
// K2: single-block inclusive scan of g_sdiff -> wbar = sigmoid(D).
// 8000 elements in 8 chunks of 1024 with a running carry.
// ---------------------------------------------------------------------------
__global__ void k2_scan_sigmoid()
{
    __shared__ float sh[1024];
    const int tid = threadIdx.x;
    float carry = 0.f;

    for (int base = 0; base < N_ROWS; base += 1024) {
        int i = base + tid;
        float v = (i < N_ROWS) ? g_sdiff[i] : 0.f;
        sh[tid] = v;
        __syncthreads();
#pragma unroll
        for (int off = 1; off < 1024; off <<= 1) {
            float t = (tid >= off) ? sh[tid - off] : 0.f;
            __syncthreads();
            sh[tid] += t;
            __syncthreads();
        }
        float Dv = sh[tid] + carry;
        if (i < N_ROWS) {
            // w1_bar = 1 / (1 + exp(-D))
            g_wbar[i] = 1.0f / (1.0f + expf(-Dv));
        }
        carry += sh[1023];
        __syncthreads();
    }
}

// ---------------------------------------------------------------------------
// K3: out[i, j] = f2[i] + (f1[i] - f2[i]) * wbar[j]
// Block per row, float4 stores. 8000 cols = 2000 float4 per row.
// wbar (32 KB) stays resident in L1/L2 across the whole kernel.
// ---------------------------------------------------------------------------
__global__ void __launch_bounds__(256) k3_outer(float* __restrict__ out)
{
    const int row = blockIdx.x;
    const float f2i = g_f2[row];
    const float df  = g_f1[row] - f2i;

    const float4* __restrict__ wb4 = (const float4*)g_wbar;
    float4* __restrict__ o4 = (float4*)(out + (size_t)row * N_ROWS);

#pragma unroll 4
    for (int j = threadIdx.x; j < N_ROWS / 4; j += 256) {
        float4 w = wb4[j];
        float4 r;
        r.x = fmaf(df, w.x, f2i);
        r.y = fmaf(df, w.y, f2i);
        r.z = fmaf(df, w.z, f2i);
        r.w = fmaf(df, w.w, f2i);
        o4[j] = r;
    }
}

// ---------------------------------------------------------------------------
extern "C" void kernel_launch(void* const* d_in, const int* in_sizes, int n_in,
                              void* d_out, int out_size)
{
    const float* x     = (const float*)d_in[0];
    const float* a1    = (const float*)d_in[1];
    const float* c1    = (const float*)d_in[2];
    const float* a2    = (const float*)d_in[3];
    const float* c2    = (const float*)d_in[4];
    const float* w_fc1 = (const float*)d_in[5];
    const float* b_fc1 = (const float*)d_in[6];
    const float* w_fc2 = (const float*)d_in[7];
    const float* b_fc2 = (const float*)d_in[8];
    float* out = (float*)d_out;

    k1_rowstats<<<(N_ROWS + 127) / 128, 128>>>(x, a1, c1, a2, c2,
                                               w_fc1, b_fc1, w_fc2, b_fc2);
    k2_scan_sigmoid<<<1, 1024>>>();
    k3_outer<<<N_ROWS, 256>>>(out);
}

// round 5
// speedup vs baseline: 1.1417x; 1.1417x over previous
#include <cuda_runtime.h>
#include <math.h>

#define N_ROWS 8000
#define D_DIM  9

// Scratch: device globals (no allocation allowed anywhere)
__device__ float g_sdiff[N_ROWS + 192];  // padded so the scan can read full float4s
__device__ float g_f1[N_ROWS];
__device__ float g_f2[N_ROWS];
__device__ float g_wbar[N_ROWS];

// ---------------------------------------------------------------------------
// K1: per-row stats with smem staging for coalesced global loads.
// Block of 256 threads handles 256 rows = 2304 floats = 576 float4 (contiguous,
// 16B-aligned since 2304 % 4 == 0 per block). Per-row reads then come from
// smem with stride 9 (gcd(9,32)=1 -> bank-conflict-free).
// ---------------------------------------------------------------------------
__global__ void __launch_bounds__(256) k1_rowstats(
    const float* __restrict__ x,
    const float* __restrict__ a1p, const float* __restrict__ c1p,
    const float* __restrict__ a2p, const float* __restrict__ c2p,
    const float* __restrict__ w1,  const float* __restrict__ b1,
    const float* __restrict__ w2,  const float* __restrict__ b2)
{
    __shared__ float s_x[256 * D_DIM];

    const int row0   = blockIdx.x * 256;
    const int n_rows = min(256, N_ROWS - row0);
    const int n_flt  = n_rows * D_DIM;

    // Coalesced staged load (float4 where possible)
    const float4* __restrict__ x4 = (const float4*)(x + (size_t)row0 * D_DIM);
    float4* s4 = (float4*)s_x;
    const int n_vec = n_flt / 4;
    for (int v = threadIdx.x; v < n_vec; v += 256) s4[v] = x4[v];
    // tail floats (n_flt may not be /4 for the last block)
    for (int t = n_vec * 4 + threadIdx.x; t < n_flt; t += 256)
        s_x[t] = x[(size_t)row0 * D_DIM + t];
    __syncthreads();

    const int r = threadIdx.x;
    if (r >= n_rows) return;
    const int i = row0 + r;

    const float a1 = a1p[0], c1 = c1p[0], a2 = a2p[0], c2 = c2p[0];
    const float inv_a1 = 1.0f / a1, inv_a2 = 1.0f / a2;

    float s1 = 0.f, s2 = 0.f, f1 = 0.f, f2 = 0.f;
#pragma unroll
    for (int d = 0; d < D_DIM; d++) {
        float xv = s_x[r * D_DIM + d];
        float t1 = (xv - c1) * inv_a1;
        float t2 = (xv - c2) * inv_a2;
        s1 = fmaf(t1, t1, s1);
        s2 = fmaf(t2, t2, s2);
        f1 = fmaf(xv, w1[d], f1);
        f2 = fmaf(xv, w2[d], f2);
    }
    g_sdiff[i] = s2 - s1;
    g_f1[i] = f1 + b1[0];
    g_f2[i] = f2 + b2[0];
}

// Zero the scan padding so out-of-range lanes contribute nothing.
__global__ void k1b_zero_pad()
{
    int i = N_ROWS + threadIdx.x;
    if (threadIdx.x < 192) g_sdiff[i] = 0.f;
}

// ---------------------------------------------------------------------------
// K2: single-pass inclusive scan of 8000 elems -> wbar = sigmoid(prefix).
// 1024 threads x 8 elems each (8192 >= 8000, padding is zero).
// Thread-serial scan -> warp shuffle scan of totals -> one smem hop for
// the 32 warp totals -> add prefix, sigmoid, coalesced float4 store.
// ---------------------------------------------------------------------------
__global__ void __launch_bounds__(1024) k2_scan_sigmoid()
{
    __shared__ float s_warp[32];

    const int tid  = threadIdx.x;
    const int lane = tid & 31;
    const int wid  = tid >> 5;

    // Load 8 contiguous elems (2 float4, coalesced: warp covers 1KB)
    const float4* __restrict__ in4 = (const float4*)g_sdiff;
    float4 va = in4[2 * tid];
    float4 vb = in4[2 * tid + 1];

    float e[8] = {va.x, va.y, va.z, va.w, vb.x, vb.y, vb.z, vb.w};
    // inclusive serial scan
#pragma unroll
    for (int k = 1; k < 8; k++) e[k] += e[k - 1];
    float tot = e[7];

    // warp-inclusive scan of thread totals
    float ws = tot;
#pragma unroll
    for (int off = 1; off < 32; off <<= 1) {
        float t = __shfl_up_sync(0xFFFFFFFFu, ws, off);
        if (lane >= off) ws += t;
    }
    if (lane == 31) s_warp[wid] = ws;
    __syncthreads();

    // warp 0 scans the 32 warp totals
    if (wid == 0) {
        float w = s_warp[lane];
#pragma unroll
        for (int off = 1; off < 32; off <<= 1) {
            float t = __shfl_up_sync(0xFFFFFFFFu, w, off);
            if (lane >= off) w += t;
        }
        s_warp[lane] = w;
    }
    __syncthreads();

    float warp_prefix = (wid > 0) ? s_warp[wid - 1] : 0.f;
    float thread_prefix = warp_prefix + (ws - tot);  // exclusive over this thread

    float o[8];
#pragma unroll
    for (int k = 0; k < 8; k++) {
        float Dv = thread_prefix + e[k];
        o[k] = 1.0f / (1.0f + expf(-Dv));
    }

    // store (guard the tail: indices 8000..8191 don't exist)
    const int base = tid * 8;
    if (base + 8 <= N_ROWS) {
        float4* __restrict__ out4 = (float4*)g_wbar;
        out4[2 * tid]     = make_float4(o[0], o[1], o[2], o[3]);
        out4[2 * tid + 1] = make_float4(o[4], o[5], o[6], o[7]);
    } else {
#pragma unroll
        for (int k = 0; k < 8; k++)
            if (base + k < N_ROWS) g_wbar[base + k] = o[k];
    }
}

// ---------------------------------------------------------------------------
// K3: out[i, j] = f2[i] + (f1[i] - f2[i]) * wbar[j]
// Two rows per block: each wbar float4 load feeds two streaming stores.
// ---------------------------------------------------------------------------
__global__ void __launch_bounds__(256) k3_outer(float* __restrict__ out)
{
    const int rowA = blockIdx.x * 2;
    const int rowB = rowA + 1;

    const float f2A = g_f2[rowA];
    const float dfA = g_f1[rowA] - f2A;
    const float f2B = g_f2[rowB];
    const float dfB = g_f1[rowB] - f2B;

    const float4* __restrict__ wb4 = (const float4*)g_wbar;
    float4* __restrict__ oA = (float4*)(out + (size_t)rowA * N_ROWS);
    float4* __restrict__ oB = (float4*)(out + (size_t)rowB * N_ROWS);

#pragma unroll 4
    for (int j = threadIdx.x; j < N_ROWS / 4; j += 256) {
        float4 w = wb4[j];
        float4 rA, rB;
        rA.x = fmaf(dfA, w.x, f2A); rA.y = fmaf(dfA, w.y, f2A);
        rA.z = fmaf(dfA, w.z, f2A); rA.w = fmaf(dfA, w.w, f2A);
        rB.x = fmaf(dfB, w.x, f2B); rB.y = fmaf(dfB, w.y, f2B);
        rB.z = fmaf(dfB, w.z, f2B); rB.w = fmaf(dfB, w.w, f2B);
        __stcs(&oA[j], rA);
        __stcs(&oB[j], rB);
    }
}

// ---------------------------------------------------------------------------
extern "C" void kernel_launch(void* const* d_in, const int* in_sizes, int n_in,
                              void* d_out, int out_size)
{
    const float* x     = (const float*)d_in[0];
    const float* a1    = (const float*)d_in[1];
    const float* c1    = (const float*)d_in[2];
    const float* a2    = (const float*)d_in[3];
    const float* c2    = (const float*)d_in[4];
    const float* w_fc1 = (const float*)d_in[5];
    const float* b_fc1 = (const float*)d_in[6];
    const float* w_fc2 = (const float*)d_in[7];
    const float* b_fc2 = (const float*)d_in[8];
    float* out = (float*)d_out;

    k1b_zero_pad<<<1, 192>>>();
    k1_rowstats<<<(N_ROWS + 255) / 256, 256>>>(x, a1, c1, a2, c2,
                                               w_fc1, b_fc1, w_fc2, b_fc2);
    k2_scan_sigmoid<<<1, 1024>>>();
    k3_outer<<<N_ROWS / 2, 256>>>(out);
}